// round 16
// baseline (speedup 1.0000x reference)
#include <cuda_runtime.h>
#include <cstdint>

// Problem constants (fixed by setup_inputs)
#define B_  16
#define C_  3
#define H_  1024
#define W_  1024
#define CP_ 35                 // control-point grid 35x35
#define HW_ (H_ * W_)
#define CHW_ (C_ * HW_)
#define BC_ (B_ * C_)
#define STEP_ (2.0f / 1023.0f) // linspace(-1,1,1024) step

// Streaming 8-byte store (evict-first): output is write-once, keep L2 for taps.
__device__ __forceinline__ void stcs_f2(float* p, float a, float b) {
    float2 v = make_float2(a, b);
    asm volatile("st.global.cs.v2.f32 [%0], {%1, %2};" :: "l"(p), "f"(v.x), "f"(v.y) : "memory");
}

// ---------------------------------------------------------------------------
// Bilinear sample with border padding from the 35x35 control grid, replicating
// the reference's exact double normalization.
// ---------------------------------------------------------------------------
__device__ __forceinline__ void sample_deformation(
    const float* __restrict__ cp, float gx, float gy,
    float& d0, float& d1)
{
    float cpx = gx * 17.0f + 17.0f;
    float cpy = gy * 17.0f + 17.0f;
    float ix = (cpx + 1.0f) * 0.5f * 34.0f;
    float iy = (cpy + 1.0f) * 0.5f * 34.0f;
    ix = fminf(fmaxf(ix, 0.0f), 34.0f);
    iy = fminf(fmaxf(iy, 0.0f), 34.0f);
    float ix0f = floorf(ix);
    float iy0f = floorf(iy);
    float wx = ix - ix0f;
    float wy = iy - iy0f;
    int ix0 = (int)ix0f;
    int iy0 = (int)iy0f;
    int ix1 = min(ix0 + 1, 34);
    int iy1 = min(iy0 + 1, 34);

    int o00 = iy0 * CP_ + ix0;
    int o01 = iy0 * CP_ + ix1;
    int o10 = iy1 * CP_ + ix0;
    int o11 = iy1 * CP_ + ix1;

    {
        float v00 = __ldg(cp + o00);
        float v01 = __ldg(cp + o01);
        float v10 = __ldg(cp + o10);
        float v11 = __ldg(cp + o11);
        float top = v00 * (1.0f - wx) + v01 * wx;
        float bot = v10 * (1.0f - wx) + v11 * wx;
        d0 = top * (1.0f - wy) + bot * wy;
    }
    {
        const float* cp1 = cp + CP_ * CP_;
        float v00 = __ldg(cp1 + o00);
        float v01 = __ldg(cp1 + o01);
        float v10 = __ldg(cp1 + o10);
        float v11 = __ldg(cp1 + o11);
        float top = v00 * (1.0f - wx) + v01 * wx;
        float bot = v10 * (1.0f - wx) + v11 * wx;
        d1 = top * (1.0f - wy) + bot * wy;
    }
}

// Per-pixel image-sampling setup: weights + 4 tap offsets.
__device__ __forceinline__ void pixel_setup(
    float gx, float gy, float d0, float d1,
    float& wx, float& omwx, float& wy, float& omwy,
    int& o00, int& o01, int& o10, int& o11)
{
    float sx = gx + d1;
    float sy = gy + d0;
    float ix = (sx + 1.0f) * 0.5f * 1023.0f;
    float iy = (sy + 1.0f) * 0.5f * 1023.0f;
    ix = fminf(fmaxf(ix, 0.0f), 1023.0f);
    iy = fminf(fmaxf(iy, 0.0f), 1023.0f);
    float ix0f = floorf(ix);
    float iy0f = floorf(iy);
    wx = ix - ix0f;
    wy = iy - iy0f;
    omwx = 1.0f - wx;
    omwy = 1.0f - wy;
    int ix0 = (int)ix0f;
    int iy0 = (int)iy0f;
    int ix1 = min(ix0 + 1, W_ - 1);
    int iy1 = min(iy0 + 1, H_ - 1);
    int r0 = iy0 * W_;
    int r1 = iy1 * W_;
    o00 = r0 + ix0;
    o01 = r0 + ix1;
    o10 = r1 + ix0;
    o11 = r1 + ix1;
}

// ---------------------------------------------------------------------------
// Fused kernel, 2 pixels (adjacent w) per thread.
// Grid: (W/512, H). Block: 256. Each thread: deformation + coords for both
// pixels once, then a flattened 48-iteration (b*c) loop of 8 tap loads + one
// float2 streaming store.
// ---------------------------------------------------------------------------
__global__ __launch_bounds__(256)
void bspline_fused2_kernel(const float* __restrict__ x,
                           const float* __restrict__ cp,
                           float* __restrict__ out,
                           float* __restrict__ def_out)
{
    int t = blockIdx.x * blockDim.x + threadIdx.x;
    int w0 = t * 2;
    int h = blockIdx.y;

    float gy  = -1.0f + (float)h * STEP_;
    float gxA = -1.0f + (float)w0 * STEP_;
    float gxB = -1.0f + (float)(w0 + 1) * STEP_;

    float d0A, d1A, d0B, d1B;
    sample_deformation(cp, gxA, gy, d0A, d1A);
    sample_deformation(cp, gxB, gy, d0B, d1B);

    int pix = h * W_ + w0;   // even -> 8B aligned
    stcs_f2(def_out + pix,        d0A, d0B);
    stcs_f2(def_out + HW_ + pix,  d1A, d1B);

    float wxA, omwxA, wyA, omwyA, wxB, omwxB, wyB, omwyB;
    int aA00, aA01, aA10, aA11, aB00, aB01, aB10, aB11;
    pixel_setup(gxA, gy, d0A, d1A, wxA, omwxA, wyA, omwyA, aA00, aA01, aA10, aA11);
    pixel_setup(gxB, gy, d0B, d1B, wxB, omwxB, wyB, omwyB, aB00, aB01, aB10, aB11);

    const float* xc = x;
    float* oc = out + pix;
#pragma unroll 2
    for (int bc = 0; bc < BC_; bc++) {
        // 8 independent tap loads -> high per-thread MLP
        float vA00 = __ldg(xc + aA00);
        float vA01 = __ldg(xc + aA01);
        float vA10 = __ldg(xc + aA10);
        float vA11 = __ldg(xc + aA11);
        float vB00 = __ldg(xc + aB00);
        float vB01 = __ldg(xc + aB01);
        float vB10 = __ldg(xc + aB10);
        float vB11 = __ldg(xc + aB11);

        float topA = vA00 * omwxA + vA01 * wxA;
        float botA = vA10 * omwxA + vA11 * wxA;
        float rA   = topA * omwyA + botA * wyA;

        float topB = vB00 * omwxB + vB01 * wxB;
        float botB = vB10 * omwxB + vB11 * wxB;
        float rB   = topB * omwyB + botB * wyB;

        stcs_f2(oc, rA, rB);

        xc += HW_;
        oc += HW_;
    }
}

// ---------------------------------------------------------------------------
extern "C" void kernel_launch(void* const* d_in, const int* in_sizes, int n_in,
                              void* d_out, int out_size)
{
    const float* x  = (const float*)d_in[0];  // (16,3,1024,1024) f32
    const float* cp = (const float*)d_in[1];  // (1,2,35,35) f32
    float* out = (float*)d_out;               // transformed(192MB) ++ def(8MB)

    float* def_out = out + (size_t)B_ * CHW_;

    dim3 blk(256, 1, 1);
    dim3 grd(W_ / 512, H_, 1);   // 2 pixels per thread along w
    bspline_fused2_kernel<<<grd, blk>>>(x, cp, out, def_out);
}